// round 9
// baseline (speedup 1.0000x reference)
#include <cuda_runtime.h>
#include <cstdint>

// Problem constants
constexpr int B_   = 8;
constexpr int H_   = 8;
constexpr int LQ_  = 1024;
constexpr int LM_  = 4096;
constexpr int DM_  = 512;
constexpr int DK_  = 64;
constexpr int TOPK_ = 32;

// Attention kernel tiling
constexpr int QT   = 32;    // queries per block (4 rows per warp)
constexpr int CK   = 128;   // key chunk (64 f32x2 pairs)
constexpr int NP   = 64;    // key pairs per chunk

// Scratch (static device arrays: allocation-free)
__device__ float g_q[B_*H_*LQ_*DK_];   // 16 MB  [B,H,LQ,Dk]
__device__ float g_k[B_*H_*LM_*DK_];   // 64 MB  [B,H,LM,Dk]
__device__ float g_v[B_*H_*LM_*DK_];   // 64 MB  [B,H,LM,Dk]
__device__ float g_x[B_*LQ_*DM_];      // 16 MB  [B,LQ,DM] pre-output-proj

// ---------------- packed f32x2 primitives (lanewise IEEE fp32) -------------
typedef unsigned long long ull;

__device__ __forceinline__ ull pack2(float lo, float hi) {
    ull d; asm("mov.b64 %0, {%1, %2};" : "=l"(d) : "f"(lo), "f"(hi)); return d;
}
__device__ __forceinline__ void unpack2(ull v, float& lo, float& hi) {
    asm("mov.b64 {%0, %1}, %2;" : "=f"(lo), "=f"(hi) : "l"(v));
}
__device__ __forceinline__ ull fma2(ull a, ull b, ull c) {
    ull d; asm("fma.rn.f32x2 %0, %1, %2, %3;" : "=l"(d) : "l"(a), "l"(b), "l"(c)); return d;
}
__device__ __forceinline__ ull mul2(ull a, ull b) {
    ull d; asm("mul.rn.f32x2 %0, %1, %2;" : "=l"(d) : "l"(a), "l"(b)); return d;
}
__device__ __forceinline__ ull add2(ull a, ull b) {
    ull d; asm("add.rn.f32x2 %0, %1, %2;" : "=l"(d) : "l"(a), "l"(b)); return d;
}

// ---------------- attention smem layout (float units) ----------------------
constexpr int OFF_QS  = 0;                      // QT*DK ull  = 4096 floats (dup Q)
constexpr int OFF_KP  = OFF_QS + QT*DK_*2;      // NP*DK ull  = 8192 floats (pair K)
constexpr int OFF_SCC = OFF_KP + NP*DK_*2;      // QT*CK uint = 4096 floats
constexpr int SMEM_FLOATS = OFF_SCC + QT*CK;
constexpr int SMEM_BYTES  = SMEM_FLOATS * 4;    // 65536 B -> 3 blocks/SM

// order-preserving float -> uint, and inverse
__device__ __forceinline__ unsigned ordu(float x) {
    unsigned u = __float_as_uint(x);
    return (u & 0x80000000u) ? ~u : (u | 0x80000000u);
}
__device__ __forceinline__ float iordu(unsigned v) {
    unsigned u = (v & 0x80000000u) ? (v ^ 0x80000000u) : ~v;
    return __uint_as_float(u);
}

// B smem row layout: per-tx pad to 10 floats -> 16 distinct banks for the
// 16 tx groups (10*tx mod 32 all distinct), 8B-aligned pairs for LDS.64.
constexpr int BROW = 160;
__device__ __forceinline__ int bswz(int n) { return (n >> 3) * 10 + (n & 7); }

// ---------------------------------------------------------------------------
// SGEMM body, 512 threads: C = A[M,512] @ W[512,512]^T + bias.
// Per-output arithmetic (values and order) IDENTICAL to rounds 2-8:
// two-level fold, k ascending. f32x2 inner loop; A duplicated in smem.
// Threads 0-255 stage A, 256-511 stage B. 4x8 outputs per thread.
// ---------------------------------------------------------------------------
__device__ __forceinline__ void gemm_body(
    const float* __restrict__ A, const float* __restrict__ W,
    const float* __restrict__ bias, float* __restrict__ C,
    int L, int head_major, int m0, int n0)
{
    __shared__ __align__(16) float AsD[2][8][256];   // duplicated A pairs
    __shared__ __align__(16) float Bs [2][8][BROW];  // padded B

    const int t   = threadIdx.x;          // 0..511
    const int tx  = t & 15;               // n-group: 8 n (4 ull)
    const int ty  = (t >> 4) & 31;        // m-group: 4 m rows
    const bool isA = (t < 256);
    const int u   = isA ? t : (t - 256);
    const int lr  = u >> 1;
    const int lc  = (u & 1) << 2;

    const float* Sp = isA ? (A + (size_t)(m0 + lr) * DM_ + lc)
                          : (W + (size_t)(n0 + lr) * DM_ + lc);
    const int bofs = bswz(lr);

    // stage k-tile 0
    {
        float4 v = *(const float4*)Sp;
        if (isA) {
            ((ull*)AsD[0][lc+0])[lr] = pack2(v.x, v.x);
            ((ull*)AsD[0][lc+1])[lr] = pack2(v.y, v.y);
            ((ull*)AsD[0][lc+2])[lr] = pack2(v.z, v.z);
            ((ull*)AsD[0][lc+3])[lr] = pack2(v.w, v.w);
        } else {
            Bs[0][lc+0][bofs] = v.x;
            Bs[0][lc+1][bofs] = v.y;
            Bs[0][lc+2][bofs] = v.z;
            Bs[0][lc+3][bofs] = v.w;
        }
    }
    __syncthreads();

    ull acc2[4][4];
    #pragma unroll
    for (int i = 0; i < 4; i++)
        #pragma unroll
        for (int j = 0; j < 4; j++) acc2[i][j] = pack2(0.f, 0.f);

    #pragma unroll 1
    for (int k0 = 0; k0 < DM_; k0 += 8) {
        const int  p    = (k0 >> 3) & 1;
        const bool more = (k0 + 8) < DM_;
        float4 v;
        if (more) v = *(const float4*)(Sp + k0 + 8);

        ull cacc2[4][4];
        #pragma unroll
        for (int k = 0; k < 8; k++) {
            ull a2[4];
            {
                const ulonglong2* ar = (const ulonglong2*)&AsD[p][k][0];
                ulonglong2 v0 = ar[ty*2];
                ulonglong2 v1 = ar[ty*2 + 1];
                a2[0] = v0.x; a2[1] = v0.y; a2[2] = v1.x; a2[3] = v1.y;
            }
            ull b2[4];
            {
                const ull* br = (const ull*)&Bs[p][k][tx*10];
                #pragma unroll
                for (int j = 0; j < 4; j++) b2[j] = br[j];
            }
            if (k == 0) {
                #pragma unroll
                for (int i = 0; i < 4; i++)
                    #pragma unroll
                    for (int j = 0; j < 4; j++)
                        cacc2[i][j] = mul2(a2[i], b2[j]);
            } else {
                #pragma unroll
                for (int i = 0; i < 4; i++)
                    #pragma unroll
                    for (int j = 0; j < 4; j++)
                        cacc2[i][j] = fma2(a2[i], b2[j], cacc2[i][j]);
            }
        }
        #pragma unroll
        for (int i = 0; i < 4; i++)
            #pragma unroll
            for (int j = 0; j < 4; j++)
                acc2[i][j] = add2(acc2[i][j], cacc2[i][j]);

        if (more) {
            const int q = p ^ 1;
            if (isA) {
                ((ull*)AsD[q][lc+0])[lr] = pack2(v.x, v.x);
                ((ull*)AsD[q][lc+1])[lr] = pack2(v.y, v.y);
                ((ull*)AsD[q][lc+2])[lr] = pack2(v.z, v.z);
                ((ull*)AsD[q][lc+3])[lr] = pack2(v.w, v.w);
            } else {
                Bs[q][lc+0][bofs] = v.x;
                Bs[q][lc+1][bofs] = v.y;
                Bs[q][lc+2][bofs] = v.z;
                Bs[q][lc+3][bofs] = v.w;
            }
        }
        __syncthreads();
    }

    #pragma unroll
    for (int i = 0; i < 4; i++) {
        int m   = m0 + ty*4 + i;
        int bb_ = m / L;
        int l   = m - bb_ * L;
        #pragma unroll
        for (int j = 0; j < 4; j++) {
            float lo, hi;
            unpack2(acc2[i][j], lo, hi);
            int n0j = n0 + tx*8 + 2*j;
            float v0 = lo + bias[n0j];
            float v1 = hi + bias[n0j + 1];
            if (head_major) {
                int hh0 = n0j >> 6, dk0 = n0j & 63;
                int hh1 = (n0j+1) >> 6, dk1 = (n0j+1) & 63;
                C[((size_t)(bb_*H_ + hh0) * L + l) * DK_ + dk0] = v0;
                C[((size_t)(bb_*H_ + hh1) * L + l) * DK_ + dk1] = v1;
            } else {
                C[(size_t)m * DM_ + n0j]     = v0;
                C[(size_t)m * DM_ + n0j + 1] = v1;
            }
        }
    }
}

// Merged Q/K/V projection: grid (64 + 256 + 256, 4), 512 threads.
__global__ void __launch_bounds__(512, 1)
qkv_gemm_kernel(const float* __restrict__ q_in, const float* __restrict__ k_in,
                const float* __restrict__ v_in,
                const float* __restrict__ Wq, const float* __restrict__ bq,
                const float* __restrict__ Wk, const float* __restrict__ bk,
                const float* __restrict__ Wv, const float* __restrict__ bv,
                float* __restrict__ pq, float* __restrict__ pk, float* __restrict__ pv)
{
    const int bx = blockIdx.x;
    const float *A, *W, *bias; float* C; int L, mblk;
    if (bx < 64)        { A = q_in; W = Wq; bias = bq; C = pq; L = LQ_; mblk = bx; }
    else if (bx < 320)  { A = k_in; W = Wk; bias = bk; C = pk; L = LM_; mblk = bx - 64; }
    else                { A = v_in; W = Wv; bias = bv; C = pv; L = LM_; mblk = bx - 320; }
    gemm_body(A, W, bias, C, L, 1, mblk * 128, blockIdx.y * 128);
}

// Output projection: plain row-major, 512 threads.
__global__ void __launch_bounds__(512, 1)
out_gemm_kernel(const float* __restrict__ A, const float* __restrict__ W,
                const float* __restrict__ bias, float* __restrict__ C)
{
    gemm_body(A, W, bias, C, LQ_, 0, blockIdx.x * 128, blockIdx.y * 128);
}

// ---------------------------------------------------------------------------
// Fused scores (f32x2 over key pairs) + EXACT top-32 (running register top-k,
// uint4 skip fast path) + softmax + V gather.
// One block per (b, h, 32-query tile); 256 threads; warp w owns rows 4w..4w+3.
// Per-(q,k) lane arithmetic: t=mul(d0);fma(d1);fma(d2);fma(d3); acc+=t per
// 4 dims, ascending — the canonical contraction of the rounds-4..8 statement.
// Selection visit order unchanged (ascending key index).
// ---------------------------------------------------------------------------
__global__ void __launch_bounds__(256, 3)
attn_topk_kernel(const float* __restrict__ gq, const float* __restrict__ gk,
                 const float* __restrict__ gv, float* __restrict__ gx)
{
    extern __shared__ float sm[];
    ull*      qsD = (ull*)(sm + OFF_QS);         // dup Q: (q,q) per dim
    ull*      kp  = (ull*)(sm + OFF_KP);         // pair K: (k[pr], k[pr+64]) per dim, swizzled
    unsigned* scC = (unsigned*)(sm + OFF_SCC);   // QT x CK ordu scores

    const int t    = threadIdx.x;
    const int lane = t & 31;
    const int w    = t >> 5;               // warp id; owns rows 4w..4w+3
    const int qt0  = blockIdx.x * QT;
    const int h    = blockIdx.y;
    const int b    = blockIdx.z;
    const unsigned FULL = 0xffffffffu;

    // score-phase ownership: key pair pr (keys pr, pr+64), queries qh..qh+7
    const int pr = t & 63;
    const int qh = (t >> 6) << 3;
    const int sw = (pr & 31) << 1;          // ull-granularity XOR swizzle

    // ---- load Q tile duplicated (32x64 -> (q,q) ull) ----
    const float4* qb4 = (const float4*)(gq + ((size_t)(b*H_ + h) * LQ_ + qt0) * DK_);
    #pragma unroll
    for (int i = t; i < QT*DK_/4; i += 256) {
        float4 qv = qb4[i];
        ull* qd = qsD + i*4;
        qd[0] = pack2(qv.x, qv.x);
        qd[1] = pack2(qv.y, qv.y);
        qd[2] = pack2(qv.z, qv.z);
        qd[3] = pack2(qv.w, qv.w);
    }

    const float* kbase = gk + (size_t)(b*H_ + h) * LM_ * DK_;

    // running top-32 state for the four rows owned by this warp
    unsigned bval[4] = {0u, 0u, 0u, 0u};
    int      bidx[4] = {0, 0, 0, 0};
    unsigned m[4]    = {0u, 0u, 0u, 0u};

    #pragma unroll 1
    for (int c0 = 0; c0 < LM_; c0 += CK) {
        __syncthreads();  // prev chunk's select done before kp/scC overwrite

        // ---- stage K chunk as packed pairs, XOR-swizzled ----
        #pragma unroll
        for (int i = t; i < NP*16; i += 256) {
            int p2 = i >> 4, col = i & 15;
            float4 k0v = ((const float4*)(kbase + (size_t)(c0 + p2)      * DK_))[col];
            float4 k1v = ((const float4*)(kbase + (size_t)(c0 + p2 + 64) * DK_))[col];
            int swp = (p2 & 31) << 1;
            ull* kr = kp + p2*DK_;
            int d0 = (col*4)     ^ swp;
            int d2 = (col*4 + 2) ^ swp;
            kr[d0]   = pack2(k0v.x, k1v.x);
            kr[d0+1] = pack2(k0v.y, k1v.y);
            kr[d2]   = pack2(k0v.z, k1v.z);
            kr[d2+1] = pack2(k0v.w, k1v.w);
        }
        __syncthreads();

        // ---- scores: thread owns key pair pr and queries qh..qh+7 ----
        {
            ull acc01[8];
            #pragma unroll
            for (int qi = 0; qi < 8; qi++) acc01[qi] = pack2(0.f, 0.f);
            const ull* kr = kp + pr*DK_;
            const ull* qr = qsD + qh*DK_;
            #pragma unroll 4
            for (int d4 = 0; d4 < 16; d4++) {
                const int d  = d4*4;
                ulonglong2 ka = *(const ulonglong2*)(kr + ((d    ) ^ sw));
                ulonglong2 kb = *(const ulonglong2*)(kr + ((d + 2) ^ sw));
                #pragma unroll
                for (int qi = 0; qi < 8; qi++) {
                    ulonglong2 qa = *(const ulonglong2*)(qr + qi*DK_ + d);
                    ulonglong2 qb = *(const ulonglong2*)(qr + qi*DK_ + d + 2);
                    ull tt = mul2(ka.x, qa.x);
                    tt = fma2(ka.y, qa.y, tt);
                    tt = fma2(kb.x, qb.x, tt);
                    tt = fma2(kb.y, qb.y, tt);
                    acc01[qi] = add2(acc01[qi], tt);
                }
            }
            #pragma unroll
            for (int qi = 0; qi < 8; qi++) {
                float lo, hi;
                unpack2(acc01[qi], lo, hi);
                scC[(qh + qi)*CK + pr]      = ordu(lo * 0.125f);   // key pr
                scC[(qh + qi)*CK + pr + 64] = ordu(hi * 0.125f);   // key pr+64
            }
        }
        __syncthreads();

        // ---- select: warp w updates running top-32 for rows 4w..4w+3 ----
        #pragma unroll 1
        for (int rr = 0; rr < 4; rr++) {
            const int rowi = 4*w + rr;
            const unsigned* srow = scC + rowi*CK;

            bool slow;
            if (c0 == 0) {
                slow = true;   // includes initial fill
            } else {
                // fast path: one uint4 per lane covers the 128-key chunk.
                // Skipping when nothing exceeds m is exactly equivalent to
                // sequential processing (m is monotone non-decreasing).
                uint4 uu = ((const uint4*)srow)[lane];
                bool any = (uu.x > m[rr]) | (uu.y > m[rr]) |
                           (uu.z > m[rr]) | (uu.w > m[rr]);
                slow = (__ballot_sync(FULL, any) != 0u);
            }

            if (slow) {
                #pragma unroll 1
                for (int bb = 0; bb < CK/32; bb++) {
                    const int i0 = c0 + bb*32;
                    unsigned u = srow[bb*32 + lane];

                    if (c0 == 0 && bb == 0) {       // initial fill
                        bval[rr] = u; bidx[rr] = lane;
                        m[rr] = __reduce_min_sync(FULL, bval[rr]);
                        continue;
                    }

                    unsigned hit = __ballot_sync(FULL, u > m[rr]);
                    while (hit) {                    // warp-uniform rare path
                        int s = __ffs(hit) - 1; hit &= hit - 1;
                        unsigned uc = __shfl_sync(FULL, u, s);
                        if (uc > m[rr]) {            // recheck vs updated m
                            int ic = i0 + s;
                            unsigned em = __ballot_sync(FULL, bval[rr] == m[rr]);
                            int el;
                            if (__popc(em) > 1) {
                                // tie on min: evict LARGER index (jax keeps lower)
                                int cb = ((em >> lane) & 1) ? bidx[rr] : -1;
                                int mx = __reduce_max_sync(FULL, cb);
                                el = __ffs(__ballot_sync(FULL,
                                        (bval[rr] == m[rr]) && (bidx[rr] == mx))) - 1;
                            } else {
                                el = __ffs(em) - 1;
                            }
                            if (lane == el) { bval[rr] = uc; bidx[rr] = ic; }
                            m[rr] = __reduce_min_sync(FULL, bval[rr]);
                        }
                    }
                }
            }
        }
    }

    // ---- softmax + weighted V gather for the four rows ----
    const float* vbase = gv + (size_t)(b*H_ + h) * LM_ * DK_;
    #pragma unroll 1
    for (int rr = 0; rr < 4; rr++) {
        float v  = iordu(bval[rr]);
        float mx = v;
        #pragma unroll
        for (int off = 16; off; off >>= 1)
            mx = fmaxf(mx, __shfl_xor_sync(FULL, mx, off));
        float e = __expf(v - mx);
        float s = e;
        #pragma unroll
        for (int off = 16; off; off >>= 1)
            s += __shfl_xor_sync(FULL, s, off);
        float wgt = e / s;

        float a0 = 0.f, a1 = 0.f;
        #pragma unroll 4
        for (int it = 0; it < TOPK_; it++) {
            float wi = __shfl_sync(FULL, wgt, it);
            int   ki = __shfl_sync(FULL, bidx[rr], it);
            const float* vr = vbase + (size_t)ki * DK_;
            a0 = fmaf(wi, vr[lane],      a0);
            a1 = fmaf(wi, vr[lane + 32], a1);
        }
        float* orow = gx + ((size_t)b * LQ_ + (qt0 + 4*w + rr)) * DM_ + h*DK_;
        orow[lane]      = a0;
        orow[lane + 32] = a1;
    }
}

// ---------------------------------------------------------------------------
extern "C" void kernel_launch(void* const* d_in, const int* in_sizes, int n_in,
                              void* d_out, int out_size)
{
    const float* query = (const float*)d_in[0];
    const float* key   = (const float*)d_in[1];
    const float* value = (const float*)d_in[2];
    const float* Wq    = (const float*)d_in[3];
    const float* bq    = (const float*)d_in[4];
    const float* Wk    = (const float*)d_in[5];
    const float* bk    = (const float*)d_in[6];
    const float* Wv    = (const float*)d_in[7];
    const float* bv    = (const float*)d_in[8];
    const float* Wo    = (const float*)d_in[9];
    const float* bo    = (const float*)d_in[10];
    float* out = (float*)d_out;

    float *pq, *pk, *pv, *px;
    cudaGetSymbolAddress((void**)&pq, g_q);
    cudaGetSymbolAddress((void**)&pk, g_k);
    cudaGetSymbolAddress((void**)&pv, g_v);
    cudaGetSymbolAddress((void**)&px, g_x);

    cudaFuncSetAttribute(attn_topk_kernel,
                         cudaFuncAttributeMaxDynamicSharedMemorySize, SMEM_BYTES);

    // merged Q/K/V projections into head-major scratch
    qkv_gemm_kernel<<<dim3(576, DM_/128), 512>>>(query, key, value,
                                                 Wq, bq, Wk, bk, Wv, bv,
                                                 pq, pk, pv);

    // fused scores + topk + softmax + gather
    attn_topk_kernel<<<dim3(LQ_/QT, H_, B_), 256, SMEM_BYTES>>>(pq, pk, pv, px);

    // output projection (plain row-major)
    out_gemm_kernel<<<dim3(B_*LQ_/128, DM_/128), 512>>>(px, Wo, bo, out);
}